// round 4
// baseline (speedup 1.0000x reference)
#include <cuda_runtime.h>
#include <cuda_fp16.h>
#include <cstddef>

#define N_NODES 100000
#define N_EDGES 1600000
#define HDIM 128
#define CDIM 40

#define SCAN_T 1024
#define SCAN_BLOCKS ((N_NODES + SCAN_T - 1) / SCAN_T)   // 98

// Scratch (device globals: allocation-free rule)
__device__ float  g_norm_out[N_NODES];
__device__ float  g_norm_in[N_NODES];
__device__ int    g_ints[3 * N_NODES];       // [deg_out | deg_in | cursor]
__device__ int    g_off[N_NODES + 1];
__device__ int    g_csr_src[N_EDGES];
__device__ int    g_bsum[SCAN_BLOCKS];
__device__ int    g_boff[SCAN_BLOCKS];
__device__ float  g_wcomb[HDIM * CDIM];
__device__ float  g_bcomb[CDIM];
__device__ __half g_xh[(size_t)N_NODES * HDIM];    // x * norm_out, fp16
__device__ __half g_h1h[(size_t)N_NODES * HDIM];   // h1 * norm_out, fp16
__device__ float  g_agg[(size_t)N_NODES * HDIM];   // gather1 output, fp32

#define DEG_OUT (g_ints)
#define DEG_IN  (g_ints + N_NODES)
#define CURSOR  (g_ints + 2 * N_NODES)

// ---------------------------------------------------------------------------
// launch 1: integer degree histogram
__global__ void deg_kernel(const int* __restrict__ src, const int* __restrict__ dst) {
    int e = blockIdx.x * blockDim.x + threadIdx.x;
    if (e < N_EDGES) {
        atomicAdd(&DEG_OUT[src[e]], 1);
        atomicAdd(&DEG_IN[dst[e]], 1);
    }
}

// launch 2: block-level inclusive scan of deg_in -> off[i+1], plus norms
__global__ void scan1_norm_kernel() {
    __shared__ int sm[SCAN_T];
    int i = blockIdx.x * SCAN_T + threadIdx.x;
    int v = (i < N_NODES) ? DEG_IN[i] : 0;
    if (i < N_NODES) {
        g_norm_out[i] = rsqrtf(fmaxf((float)DEG_OUT[i], 1.0f));
        g_norm_in[i]  = rsqrtf(fmaxf((float)v, 1.0f));
    }
    sm[threadIdx.x] = v;
    __syncthreads();
    for (int ofs = 1; ofs < SCAN_T; ofs <<= 1) {
        int t = (threadIdx.x >= ofs) ? sm[threadIdx.x - ofs] : 0;
        __syncthreads();
        sm[threadIdx.x] += t;
        __syncthreads();
    }
    if (i < N_NODES) g_off[i + 1] = sm[threadIdx.x];
    if (threadIdx.x == SCAN_T - 1) g_bsum[blockIdx.x] = sm[threadIdx.x];
    if (i == 0) g_off[0] = 0;
}

// launch 3: scan of block sums
__global__ void scan2_kernel() {
    __shared__ int sm[128];
    int v = (threadIdx.x < SCAN_BLOCKS) ? g_bsum[threadIdx.x] : 0;
    sm[threadIdx.x] = v;
    __syncthreads();
    for (int ofs = 1; ofs < 128; ofs <<= 1) {
        int t = (threadIdx.x >= ofs) ? sm[threadIdx.x - ofs] : 0;
        __syncthreads();
        sm[threadIdx.x] += t;
        __syncthreads();
    }
    if (threadIdx.x < SCAN_BLOCKS)
        g_boff[threadIdx.x] = (threadIdx.x == 0) ? 0 : sm[threadIdx.x - 1];
}

// launch 4: scan epilogue + fp16 conversion of x*norm_out (fused)
__global__ void __launch_bounds__(256)
scan3_conv_kernel(const float* __restrict__ x) {
    int t = blockIdx.x * blockDim.x + threadIdx.x;
    if (t < N_NODES) g_off[t + 1] += g_boff[t >> 10];   // SCAN_T == 1024

    int node = t >> 5;
    int lane = t & 31;
    if (node < N_NODES) {
        float4 v = __ldg((const float4*)x + (size_t)node * 32 + lane);
        float no = g_norm_out[node];
        __half2 p0 = __floats2half2_rn(v.x * no, v.y * no);
        __half2 p1 = __floats2half2_rn(v.z * no, v.w * no);
        uint2 w;
        w.x = *reinterpret_cast<unsigned*>(&p0);
        w.y = *reinterpret_cast<unsigned*>(&p1);
        ((uint2*)g_xh)[(size_t)node * 32 + lane] = w;
    }
}

// launch 5: CSR fill (bucket src ids by dst)
__global__ void fill_csr_kernel(const int* __restrict__ src, const int* __restrict__ dst) {
    int e = blockIdx.x * blockDim.x + threadIdx.x;
    if (e < N_EDGES) {
        int d = dst[e];
        int pos = g_off[d] + atomicAdd(&CURSOR[d], 1);
        g_csr_src[pos] = src[e];
    }
}

// ---------------------------------------------------------------------------
// helper: accumulate one fp16 row (4 halves per lane) into float4
__device__ __forceinline__ void acc_half_row(const uint2* __restrict__ base,
                                             int s, int lane, float4& acc) {
    uint2 r = __ldg(base + (size_t)s * 32 + lane);
    __half2 h0 = *reinterpret_cast<__half2*>(&r.x);
    __half2 h1 = *reinterpret_cast<__half2*>(&r.y);
    float2 f0 = __half22float2(h0);
    float2 f1 = __half22float2(h1);
    acc.x += f0.x; acc.y += f0.y; acc.z += f1.x; acc.w += f1.y;
}

// launch 6 (PROFILED SLOT): gather1: agg[n,:] = sum_{s in N_in(n)} xh[s,:]
__global__ void __launch_bounds__(256)
gather1_kernel(float* __restrict__ agg) {
    int t    = blockIdx.x * blockDim.x + threadIdx.x;
    int node = t >> 5;
    int lane = t & 31;
    if (node >= N_NODES) return;

    int beg = g_off[node];
    int end = g_off[node + 1];
    const uint2* in = (const uint2*)g_xh;

    float4 acc = make_float4(0.f, 0.f, 0.f, 0.f);
    int i = beg;
    for (; i + 8 <= end; i += 8) {
#pragma unroll
        for (int u = 0; u < 8; u++) acc_half_row(in, g_csr_src[i + u], lane, acc);
    }
    for (; i < end; i++) acc_half_row(in, g_csr_src[i], lane, acc);

    ((float4*)agg)[(size_t)node * 32 + lane] = acc;
}

// ---------------------------------------------------------------------------
// launch 7: GEMM1: h1h[n,:] = fp16( relu((agg[n,:]*norm_in[n]) @ W1 + b1) * norm_out[n] )
__global__ void __launch_bounds__(256)
gemm_l1_kernel(const float* __restrict__ in, const float* __restrict__ W,
               const float* __restrict__ bias) {
    __shared__ float Xs[64][HDIM + 4];

    const int tid = threadIdx.x;
    const int block_row = blockIdx.x * 64;

#pragma unroll
    for (int t = 0; t < 8; t++) {
        int idx = tid + t * 256;
        int r   = idx >> 5;
        int c4  = (idx & 31) << 2;
        int n   = block_row + r;
        float4 v = make_float4(0.f, 0.f, 0.f, 0.f);
        if (n < N_NODES) {
            v = *(const float4*)(in + (size_t)n * HDIM + c4);
            float s = g_norm_in[n];
            v.x *= s; v.y *= s; v.z *= s; v.w *= s;
        }
        *(float4*)&Xs[r][c4] = v;
    }
    __syncthreads();

    const int tx = tid & 15;
    const int ty = tid >> 4;

    float acc[4][8];
#pragma unroll
    for (int i = 0; i < 4; i++)
#pragma unroll
        for (int j = 0; j < 8; j++) acc[i][j] = 0.f;

#pragma unroll 8
    for (int k = 0; k < HDIM; k++) {
        float4 w0 = __ldg((const float4*)(W + (size_t)k * HDIM + tx * 8));
        float4 w1 = __ldg((const float4*)(W + (size_t)k * HDIM + tx * 8 + 4));
        float xv[4];
#pragma unroll
        for (int i = 0; i < 4; i++) xv[i] = Xs[ty * 4 + i][k];
#pragma unroll
        for (int i = 0; i < 4; i++) {
            acc[i][0] = fmaf(xv[i], w0.x, acc[i][0]);
            acc[i][1] = fmaf(xv[i], w0.y, acc[i][1]);
            acc[i][2] = fmaf(xv[i], w0.z, acc[i][2]);
            acc[i][3] = fmaf(xv[i], w0.w, acc[i][3]);
            acc[i][4] = fmaf(xv[i], w1.x, acc[i][4]);
            acc[i][5] = fmaf(xv[i], w1.y, acc[i][5]);
            acc[i][6] = fmaf(xv[i], w1.z, acc[i][6]);
            acc[i][7] = fmaf(xv[i], w1.w, acc[i][7]);
        }
    }

    float4 bv0 = __ldg((const float4*)(bias + tx * 8));
    float4 bv1 = __ldg((const float4*)(bias + tx * 8 + 4));

#pragma unroll
    for (int i = 0; i < 4; i++) {
        int n = block_row + ty * 4 + i;
        if (n < N_NODES) {
            float no = g_norm_out[n];
            float r0 = fmaxf(acc[i][0] + bv0.x, 0.f) * no;
            float r1 = fmaxf(acc[i][1] + bv0.y, 0.f) * no;
            float r2 = fmaxf(acc[i][2] + bv0.z, 0.f) * no;
            float r3 = fmaxf(acc[i][3] + bv0.w, 0.f) * no;
            float r4 = fmaxf(acc[i][4] + bv1.x, 0.f) * no;
            float r5 = fmaxf(acc[i][5] + bv1.y, 0.f) * no;
            float r6 = fmaxf(acc[i][6] + bv1.z, 0.f) * no;
            float r7 = fmaxf(acc[i][7] + bv1.w, 0.f) * no;
            __half2 p0 = __floats2half2_rn(r0, r1);
            __half2 p1 = __floats2half2_rn(r2, r3);
            __half2 p2 = __floats2half2_rn(r4, r5);
            __half2 p3 = __floats2half2_rn(r6, r7);
            uint4 wv;
            wv.x = *reinterpret_cast<unsigned*>(&p0);
            wv.y = *reinterpret_cast<unsigned*>(&p1);
            wv.z = *reinterpret_cast<unsigned*>(&p2);
            wv.w = *reinterpret_cast<unsigned*>(&p3);
            *(uint4*)(g_h1h + (size_t)n * HDIM + tx * 8) = wv;
        }
    }
}

// ---------------------------------------------------------------------------
// launch 8: Wcomb = W2 @ Wfc (blocks 0..127), bcomb = b2 @ Wfc + bfc (block 128)
__global__ void wcomb_kernel(const float* __restrict__ W2, const float* __restrict__ Wfc,
                             const float* __restrict__ b2, const float* __restrict__ bfc) {
    __shared__ float row[HDIM];
    int j = blockIdx.x;
    const float* srcrow = (j < HDIM) ? (W2 + j * HDIM) : b2;
    for (int k = threadIdx.x; k < HDIM; k += blockDim.x) row[k] = srcrow[k];
    __syncthreads();
    int c = threadIdx.x;
    if (c < CDIM) {
        float acc = (j < HDIM) ? 0.f : bfc[c];
#pragma unroll 8
        for (int k = 0; k < HDIM; k++)
            acc = fmaf(row[k], Wfc[k * CDIM + c], acc);
        if (j < HDIM) g_wcomb[j * CDIM + c] = acc;
        else          g_bcomb[c] = acc;
    }
}

// ---------------------------------------------------------------------------
// launch 9: fused gather2 + FC:
//   out[n, c] = (sum_{s in N_in(n)} h1h[s,:]) * norm_in[n] @ Wcomb[:,c] + bcomb[c]
__global__ void __launch_bounds__(256)
gather2_fc_kernel(float* __restrict__ out) {
    __shared__ float sm[8][HDIM + 4];
    __shared__ float Ws[HDIM * CDIM];
    __shared__ float bs[CDIM];

    const int tid  = threadIdx.x;
    const int wid  = tid >> 5;
    const int lane = tid & 31;
    const int node = blockIdx.x * 8 + wid;

    for (int i = tid; i < HDIM * CDIM; i += 256) Ws[i] = g_wcomb[i];
    if (tid < CDIM) bs[tid] = g_bcomb[tid];

    if (node < N_NODES) {
        int beg = g_off[node];
        int end = g_off[node + 1];
        const uint2* in = (const uint2*)g_h1h;

        float4 acc = make_float4(0.f, 0.f, 0.f, 0.f);
        int i = beg;
        for (; i + 8 <= end; i += 8) {
#pragma unroll
            for (int u = 0; u < 8; u++) acc_half_row(in, g_csr_src[i + u], lane, acc);
        }
        for (; i < end; i++) acc_half_row(in, g_csr_src[i], lane, acc);

        float ni = g_norm_in[node];
        acc.x *= ni; acc.y *= ni; acc.z *= ni; acc.w *= ni;
        *(float4*)&sm[wid][lane * 4] = acc;
    }
    __syncthreads();

    if (node < N_NODES) {
        // lane computes col c0 = lane; lanes 0..7 also col c1 = 32+lane
        float a0 = 0.f, a1 = 0.f;
        const int c0 = lane;
        const int c1 = 32 + lane;
#pragma unroll 8
        for (int j = 0; j < HDIM; j++) {
            float xv = sm[wid][j];
            a0 = fmaf(xv, Ws[j * CDIM + c0], a0);
            if (lane < 8) a1 = fmaf(xv, Ws[j * CDIM + c1], a1);
        }
        out[(size_t)node * CDIM + c0] = a0 + bs[c0];
        if (lane < 8) out[(size_t)node * CDIM + c1] = a1 + bs[c1];
    }
}

// ---------------------------------------------------------------------------
extern "C" void kernel_launch(void* const* d_in, const int* in_sizes, int n_in,
                              void* d_out, int out_size) {
    const float* x   = (const float*)d_in[0];
    const int*   ei  = (const int*)  d_in[1];
    const float* W1  = (const float*)d_in[2];
    const float* b1  = (const float*)d_in[3];
    const float* W2  = (const float*)d_in[4];
    const float* b2  = (const float*)d_in[5];
    const float* Wfc = (const float*)d_in[6];
    const float* bfc = (const float*)d_in[7];
    float* out = (float*)d_out;

    const int* src = ei;            // edge_index row 0
    const int* dst = ei + N_EDGES;  // edge_index row 1

    int* p_ints;
    float* p_agg;
    cudaGetSymbolAddress((void**)&p_ints, g_ints);
    cudaGetSymbolAddress((void**)&p_agg,  g_agg);

    const int conv_blocks = (int)(((long long)N_NODES * 32 + 255) / 256);  // 12500
    const int agg_blocks  = conv_blocks;
    const int gemm_blocks = (N_NODES + 63) / 64;

    // launch 0: zero [deg_out | deg_in | cursor]
    cudaMemsetAsync(p_ints, 0, 3 * N_NODES * sizeof(int));
    // 1: degrees
    deg_kernel<<<(N_EDGES + 255) / 256, 256>>>(src, dst);
    // 2: block scan + norms
    scan1_norm_kernel<<<SCAN_BLOCKS, SCAN_T>>>();
    // 3: block-sum scan
    scan2_kernel<<<1, 128>>>();
    // 4: scan epilogue + x*norm_out -> fp16
    scan3_conv_kernel<<<conv_blocks, 256>>>(x);
    // 5: CSR fill
    fill_csr_kernel<<<(N_EDGES + 255) / 256, 256>>>(src, dst);
    // 6 (profiled): gather1
    gather1_kernel<<<agg_blocks, 256>>>(p_agg);
    // 7: layer-1 GEMM (fp16 epilogue)
    gemm_l1_kernel<<<gemm_blocks, 256>>>(p_agg, W1, b1);
    // 8: folded weights
    wcomb_kernel<<<HDIM + 1, 64>>>(W2, Wfc, b2, bfc);
    // 9: fused gather2 + FC
    gather2_fc_kernel<<<(N_NODES + 7) / 8, 256>>>(out);
}

// round 5
// speedup vs baseline: 1.3275x; 1.3275x over previous
#include <cuda_runtime.h>
#include <cuda_fp16.h>
#include <cstddef>

#define N_NODES 100000
#define N_EDGES 1600000
#define HDIM 128
#define CDIM 40

#define SCAN_T 1024
#define SCAN_BLOCKS ((N_NODES + SCAN_T - 1) / SCAN_T)   // 98

// ---- device scratch (allocation-free rule) ----
__device__ float  g_norm_out[N_NODES];
__device__ float  g_norm_in[N_NODES];
__device__ int    g_ints[3 * N_NODES + 128];   // [deg_out | deg_in | cursor | scan flags]
__device__ int    g_off[N_NODES + 1];
__device__ int    g_csr_src[N_EDGES];
__device__ int    g_scan_agg[SCAN_BLOCKS];
__device__ int    g_scan_pref[SCAN_BLOCKS];
__device__ float  g_wcomb[HDIM * CDIM];
__device__ float  g_bcomb[CDIM];
__device__ __half g_w1ht[HDIM * HDIM];             // W1^T fp16: [n][k]
__device__ __half g_xh[(size_t)N_NODES * HDIM];    // x * norm_out, fp16
__device__ __half g_a1h[(size_t)N_NODES * HDIM];   // gather1 * norm_in, fp16
__device__ __half g_h1h[(size_t)N_NODES * HDIM];   // relu(...)*norm_out, fp16

#define DEG_OUT (g_ints)
#define DEG_IN  (g_ints + N_NODES)
#define CURSOR  (g_ints + 2 * N_NODES)
#define SFLAG   (g_ints + 3 * N_NODES)

// ---------------------------------------------------------------------------
// K1: integer degree histogram
__global__ void deg_kernel(const int* __restrict__ src, const int* __restrict__ dst) {
    int e = blockIdx.x * blockDim.x + threadIdx.x;
    if (e < N_EDGES) {
        atomicAdd(&DEG_OUT[src[e]], 1);
        atomicAdd(&DEG_IN[dst[e]], 1);
    }
}

// ---------------------------------------------------------------------------
// K2: single-pass decoupled-lookback scan of deg_in -> g_off, plus norms.
// 98 blocks (all resident simultaneously on 148 SMs -> lookback is safe).
__global__ void __launch_bounds__(SCAN_T)
scan_norm_kernel() {
    __shared__ int sm[SCAN_T];
    __shared__ int s_prefix;
    const int b = blockIdx.x;
    const int tid = threadIdx.x;
    const int i = b * SCAN_T + tid;

    int v = (i < N_NODES) ? DEG_IN[i] : 0;
    if (i < N_NODES) {
        g_norm_out[i] = rsqrtf(fmaxf((float)DEG_OUT[i], 1.0f));
        g_norm_in[i]  = rsqrtf(fmaxf((float)v, 1.0f));
    }
    sm[tid] = v;
    __syncthreads();
    for (int ofs = 1; ofs < SCAN_T; ofs <<= 1) {
        int t = (tid >= ofs) ? sm[tid - ofs] : 0;
        __syncthreads();
        sm[tid] += t;
        __syncthreads();
    }

    if (tid == 0) {
        int total = sm[SCAN_T - 1];
        g_scan_agg[b] = total;
        __threadfence();
        atomicExch(&SFLAG[b], 1);

        int p = 0;
        for (int j = b - 1; j >= 0; --j) {
            int f;
            do { f = atomicAdd(&SFLAG[j], 0); } while (f == 0);
            __threadfence();
            if (f == 2) { p += g_scan_pref[j]; break; }
            p += g_scan_agg[j];
        }
        g_scan_pref[b] = p + total;
        __threadfence();
        atomicExch(&SFLAG[b], 2);
        s_prefix = p;
    }
    __syncthreads();

    if (i < N_NODES) g_off[i + 1] = sm[tid] + s_prefix;
    if (i == 0) g_off[0] = 0;
}

// ---------------------------------------------------------------------------
// K3: fused — CSR fill + x->fp16 conversion + W1 transpose fp16 + Wcomb/bcomb
#define FILL_B  ((N_EDGES + 255) / 256)        // 6250
#define CONV_B  ((N_NODES * 32 + 255) / 256)   // 12500
#define W1T_B   ((HDIM * HDIM) / 256)          // 64
#define WC_B    (HDIM + 1)                     // 129
#define K3_GRID (FILL_B + CONV_B + W1T_B + WC_B)

__global__ void __launch_bounds__(256)
fill_conv_prep_kernel(const int* __restrict__ src, const int* __restrict__ dst,
                      const float* __restrict__ x,
                      const float* __restrict__ W1,
                      const float* __restrict__ W2, const float* __restrict__ Wfc,
                      const float* __restrict__ b2, const float* __restrict__ bfc) {
    const int bid = blockIdx.x;
    const int tid = threadIdx.x;

    if (bid < FILL_B) {
        int e = bid * 256 + tid;
        if (e < N_EDGES) {
            int d = dst[e];
            int pos = g_off[d] + atomicAdd(&CURSOR[d], 1);
            g_csr_src[pos] = src[e];
        }
    } else if (bid < FILL_B + CONV_B) {
        int t = (bid - FILL_B) * 256 + tid;
        int node = t >> 5;
        int lane = t & 31;
        if (node < N_NODES) {
            float4 v = __ldg((const float4*)x + (size_t)node * 32 + lane);
            float no = g_norm_out[node];
            __half2 p0 = __floats2half2_rn(v.x * no, v.y * no);
            __half2 p1 = __floats2half2_rn(v.z * no, v.w * no);
            uint2 w;
            w.x = *reinterpret_cast<unsigned*>(&p0);
            w.y = *reinterpret_cast<unsigned*>(&p1);
            ((uint2*)g_xh)[(size_t)node * 32 + lane] = w;
        }
    } else if (bid < FILL_B + CONV_B + W1T_B) {
        int idx = (bid - FILL_B - CONV_B) * 256 + tid;   // over 16384 elems
        int k = idx >> 7;
        int n = idx & 127;
        g_w1ht[n * HDIM + k] = __float2half_rn(W1[k * HDIM + n]);
    } else {
        int j = bid - FILL_B - CONV_B - W1T_B;           // 0..128
        __shared__ float row[HDIM];
        const float* srcrow = (j < HDIM) ? (W2 + j * HDIM) : b2;
        if (tid < HDIM) row[tid] = srcrow[tid];
        __syncthreads();
        if (tid < CDIM) {
            float acc = (j < HDIM) ? 0.f : bfc[tid];
#pragma unroll 8
            for (int k = 0; k < HDIM; k++)
                acc = fmaf(row[k], Wfc[k * CDIM + tid], acc);
            if (j < HDIM) g_wcomb[j * CDIM + tid] = acc;
            else          g_bcomb[tid] = acc;
        }
    }
}

// ---------------------------------------------------------------------------
// helper: accumulate one fp16 row (4 halves per lane) into float4
__device__ __forceinline__ void acc_half_row(const uint2* __restrict__ base,
                                             int s, int lane, float4& acc) {
    uint2 r = __ldg(base + (size_t)s * 32 + lane);
    __half2 h0 = *reinterpret_cast<__half2*>(&r.x);
    __half2 h1 = *reinterpret_cast<__half2*>(&r.y);
    float2 f0 = __half22float2(h0);
    float2 f1 = __half22float2(h1);
    acc.x += f0.x; acc.y += f0.y; acc.z += f1.x; acc.w += f1.y;
}

// K4 (PROFILED SLOT): gather1: a1h[n,:] = fp16( norm_in[n] * sum_{s} xh[s,:] )
__global__ void __launch_bounds__(256)
gather1_kernel() {
    int t    = blockIdx.x * blockDim.x + threadIdx.x;
    int node = t >> 5;
    int lane = t & 31;
    if (node >= N_NODES) return;

    int beg = g_off[node];
    int end = g_off[node + 1];
    const uint2* in = (const uint2*)g_xh;

    float4 acc = make_float4(0.f, 0.f, 0.f, 0.f);
    int i = beg;
    for (; i + 8 <= end; i += 8) {
#pragma unroll
        for (int u = 0; u < 8; u++) acc_half_row(in, g_csr_src[i + u], lane, acc);
    }
    for (; i < end; i++) acc_half_row(in, g_csr_src[i], lane, acc);

    float ni = g_norm_in[node];
    __half2 p0 = __floats2half2_rn(acc.x * ni, acc.y * ni);
    __half2 p1 = __floats2half2_rn(acc.z * ni, acc.w * ni);
    uint2 w;
    w.x = *reinterpret_cast<unsigned*>(&p0);
    w.y = *reinterpret_cast<unsigned*>(&p1);
    ((uint2*)g_a1h)[(size_t)node * 32 + lane] = w;
}

// ---------------------------------------------------------------------------
// K5: HMMA GEMM: h1h[n,:] = fp16( relu(a1h[n,:] @ W1 + b1) * norm_out[n] )
// Block tile 128x128, 8 warps (4 M-groups x 2 N-groups), warp tile 32x64.
// mma.sync.m16n8k16 f16 x f16 -> f32. A and W^T tiles in padded smem.
#define APAD 136      // halves per smem row (272 B -> bank-conflict-free frags)
#define GEMM_SMEM (2 * HDIM * APAD * (int)sizeof(__half))

__global__ void __launch_bounds__(256)
gemm_hmma_kernel(const float* __restrict__ bias) {
    extern __shared__ __half smem[];
    __half* As = smem;                    // [128][APAD]
    __half* Ws = smem + HDIM * APAD;      // [128][APAD]  (W1^T: [n][k])
    __shared__ float bs[HDIM];

    const int tid = threadIdx.x;
    const int block_row = blockIdx.x * 128;

    if (tid < HDIM) bs[tid] = bias[tid];

    // stage A (zero-padded past N_NODES) and W^T
#pragma unroll
    for (int t = 0; t < 8; t++) {
        int idx = tid + t * 256;          // uint4 index, 2048 total
        int r   = idx >> 4;               // row 0..127
        int c8  = (idx & 15) << 3;        // half col 0,8,...,120
        int n   = block_row + r;
        uint4 v = make_uint4(0u, 0u, 0u, 0u);
        if (n < N_NODES) v = *(const uint4*)(g_a1h + (size_t)n * HDIM + c8);
        *(uint4*)(As + r * APAD + c8) = v;
        uint4 wv = *(const uint4*)(g_w1ht + r * HDIM + c8);
        *(uint4*)(Ws + r * APAD + c8) = wv;
    }
    __syncthreads();

    const int warp  = tid >> 5;
    const int lane  = tid & 31;
    const int warpM = warp & 3;           // 4 groups of 32 rows
    const int warpN = warp >> 2;          // 2 groups of 64 cols
    const int lr    = lane >> 2;          // 0..7
    const int lc    = (lane & 3) << 1;    // 0,2,4,6

    float acc[2][8][4];
#pragma unroll
    for (int m = 0; m < 2; m++)
#pragma unroll
        for (int n = 0; n < 8; n++)
#pragma unroll
            for (int q = 0; q < 4; q++) acc[m][n][q] = 0.f;

#pragma unroll
    for (int k16 = 0; k16 < 8; k16++) {
        const int kb = k16 * 16 + lc;
        unsigned a[2][4];
#pragma unroll
        for (int m = 0; m < 2; m++) {
            const __half* ap = As + (warpM * 32 + m * 16 + lr) * APAD;
            a[m][0] = *(const unsigned*)(ap + kb);
            a[m][1] = *(const unsigned*)(ap + 8 * APAD + kb);
            a[m][2] = *(const unsigned*)(ap + kb + 8);
            a[m][3] = *(const unsigned*)(ap + 8 * APAD + kb + 8);
        }
#pragma unroll
        for (int n = 0; n < 8; n++) {
            const __half* bp = Ws + (warpN * 64 + n * 8 + lr) * APAD + kb;
            unsigned b0 = *(const unsigned*)(bp);
            unsigned b1 = *(const unsigned*)(bp + 8);
#pragma unroll
            for (int m = 0; m < 2; m++) {
                asm volatile(
                    "mma.sync.aligned.m16n8k16.row.col.f32.f16.f16.f32 "
                    "{%0,%1,%2,%3}, {%4,%5,%6,%7}, {%8,%9}, {%0,%1,%2,%3};"
                    : "+f"(acc[m][n][0]), "+f"(acc[m][n][1]),
                      "+f"(acc[m][n][2]), "+f"(acc[m][n][3])
                    : "r"(a[m][0]), "r"(a[m][1]), "r"(a[m][2]), "r"(a[m][3]),
                      "r"(b0), "r"(b1));
            }
        }
    }

    // epilogue: +bias, relu, *norm_out, fp16 store
#pragma unroll
    for (int m = 0; m < 2; m++) {
        int r0 = block_row + warpM * 32 + m * 16 + lr;
        int r1 = r0 + 8;
        float no0 = (r0 < N_NODES) ? g_norm_out[r0] : 0.f;
        float no1 = (r1 < N_NODES) ? g_norm_out[r1] : 0.f;
#pragma unroll
        for (int n = 0; n < 8; n++) {
            int col = warpN * 64 + n * 8 + lc;
            float bb0 = bs[col], bb1 = bs[col + 1];
            if (r0 < N_NODES) {
                __half2 h = __floats2half2_rn(fmaxf(acc[m][n][0] + bb0, 0.f) * no0,
                                              fmaxf(acc[m][n][1] + bb1, 0.f) * no0);
                *(__half2*)(g_h1h + (size_t)r0 * HDIM + col) = h;
            }
            if (r1 < N_NODES) {
                __half2 h = __floats2half2_rn(fmaxf(acc[m][n][2] + bb0, 0.f) * no1,
                                              fmaxf(acc[m][n][3] + bb1, 0.f) * no1);
                *(__half2*)(g_h1h + (size_t)r1 * HDIM + col) = h;
            }
        }
    }
}

// ---------------------------------------------------------------------------
// K6: fused gather2 + FC:
//   out[n, c] = (sum_{s} h1h[s,:]) * norm_in[n] @ Wcomb[:,c] + bcomb[c]
__global__ void __launch_bounds__(256)
gather2_fc_kernel(float* __restrict__ out) {
    __shared__ float sm[8][HDIM + 4];
    __shared__ float Ws[HDIM * CDIM];
    __shared__ float bsh[CDIM];

    const int tid  = threadIdx.x;
    const int wid  = tid >> 5;
    const int lane = tid & 31;
    const int node = blockIdx.x * 8 + wid;

    for (int i = tid; i < HDIM * CDIM; i += 256) Ws[i] = g_wcomb[i];
    if (tid < CDIM) bsh[tid] = g_bcomb[tid];

    if (node < N_NODES) {
        int beg = g_off[node];
        int end = g_off[node + 1];
        const uint2* in = (const uint2*)g_h1h;

        float4 acc = make_float4(0.f, 0.f, 0.f, 0.f);
        int i = beg;
        for (; i + 8 <= end; i += 8) {
#pragma unroll
            for (int u = 0; u < 8; u++) acc_half_row(in, g_csr_src[i + u], lane, acc);
        }
        for (; i < end; i++) acc_half_row(in, g_csr_src[i], lane, acc);

        float ni = g_norm_in[node];
        acc.x *= ni; acc.y *= ni; acc.z *= ni; acc.w *= ni;
        *(float4*)&sm[wid][lane * 4] = acc;
    }
    __syncthreads();

    if (node < N_NODES) {
        float a0 = 0.f, a1 = 0.f;
        const int c0 = lane;
        const int c1 = 32 + lane;
#pragma unroll 8
        for (int j = 0; j < HDIM; j++) {
            float xv = sm[wid][j];
            a0 = fmaf(xv, Ws[j * CDIM + c0], a0);
            if (lane < 8) a1 = fmaf(xv, Ws[j * CDIM + c1], a1);
        }
        out[(size_t)node * CDIM + c0] = a0 + bsh[c0];
        if (lane < 8) out[(size_t)node * CDIM + c1] = a1 + bsh[c1];
    }
}

// ---------------------------------------------------------------------------
extern "C" void kernel_launch(void* const* d_in, const int* in_sizes, int n_in,
                              void* d_out, int out_size) {
    const float* x   = (const float*)d_in[0];
    const int*   ei  = (const int*)  d_in[1];
    const float* W1  = (const float*)d_in[2];
    const float* b1  = (const float*)d_in[3];
    const float* W2  = (const float*)d_in[4];
    const float* b2  = (const float*)d_in[5];
    const float* Wfc = (const float*)d_in[6];
    const float* bfc = (const float*)d_in[7];
    float* out = (float*)d_out;

    const int* src = ei;            // edge_index row 0
    const int* dst = ei + N_EDGES;  // edge_index row 1

    int* p_ints;
    cudaGetSymbolAddress((void**)&p_ints, g_ints);

    static bool attr_set = false;
    if (!attr_set) {
        cudaFuncSetAttribute(gemm_hmma_kernel,
                             cudaFuncAttributeMaxDynamicSharedMemorySize, GEMM_SMEM);
        attr_set = true;
    }

    const int agg_blocks = (N_NODES * 32 + 255) / 256;   // 12500

    // zero [deg_out | deg_in | cursor | scan flags]  (memset: not a kernel node)
    cudaMemsetAsync(p_ints, 0, (3 * N_NODES + 128) * sizeof(int));
    // K1: degrees
    deg_kernel<<<(N_EDGES + 255) / 256, 256>>>(src, dst);
    // K2: lookback scan + norms
    scan_norm_kernel<<<SCAN_BLOCKS, SCAN_T>>>();
    // K3: CSR fill + x->fp16 + W1^T fp16 + Wcomb/bcomb
    fill_conv_prep_kernel<<<K3_GRID, 256>>>(src, dst, x, W1, W2, Wfc, b2, bfc);
    // K4 (profiled): gather1 -> a1h fp16
    gather1_kernel<<<agg_blocks, 256>>>();
    // K5: tensor-core GEMM -> h1h fp16
    gemm_hmma_kernel<<<(N_NODES + 127) / 128, 256, GEMM_SMEM>>>(b1);
    // K6: fused gather2 + FC
    gather2_fc_kernel<<<(N_NODES + 7) / 8, 256>>>(out);
}

// round 6
// speedup vs baseline: 1.3285x; 1.0008x over previous
#include <cuda_runtime.h>
#include <cuda_fp16.h>
#include <cstddef>

#define N_NODES 100000
#define N_EDGES 1600000
#define HDIM 128
#define CDIM 40

#define SCAN_T 1024
#define SCAN_BLOCKS ((N_NODES + SCAN_T - 1) / SCAN_T)   // 98

// ---- device scratch (allocation-free rule) ----
__device__ float  g_norm_out[N_NODES];
__device__ float  g_norm_in[N_NODES];
__device__ int    g_ints[3 * N_NODES + 128];   // [deg_out | deg_in | cursor | scan flags]
__device__ int    g_off[N_NODES + 1];
__device__ int    g_csr_src[N_EDGES];
__device__ int    g_scan_agg[SCAN_BLOCKS];
__device__ int    g_scan_pref[SCAN_BLOCKS];
__device__ float  g_wcomb[HDIM * CDIM];
__device__ float  g_bcomb[CDIM];
__device__ __half g_w1ht[HDIM * HDIM];             // W1^T fp16: [n][k]
__device__ __half g_a1h[(size_t)N_NODES * HDIM];   // gather1 * norm_in, fp16
__device__ __half g_h1h[(size_t)N_NODES * HDIM];   // relu(...)*norm_out, fp16

#define DEG_OUT (g_ints)
#define DEG_IN  (g_ints + N_NODES)
#define CURSOR  (g_ints + 2 * N_NODES)
#define SFLAG   (g_ints + 3 * N_NODES)

// ---------------------------------------------------------------------------
// K1: integer degree histogram
__global__ void deg_kernel(const int* __restrict__ src, const int* __restrict__ dst) {
    int e = blockIdx.x * blockDim.x + threadIdx.x;
    if (e < N_EDGES) {
        atomicAdd(&DEG_OUT[src[e]], 1);
        atomicAdd(&DEG_IN[dst[e]], 1);
    }
}

// ---------------------------------------------------------------------------
// K2: single-pass decoupled-lookback scan of deg_in -> g_off, plus norms.
__global__ void __launch_bounds__(SCAN_T)
scan_norm_kernel() {
    __shared__ int sm[SCAN_T];
    __shared__ int s_prefix;
    const int b = blockIdx.x;
    const int tid = threadIdx.x;
    const int i = b * SCAN_T + tid;

    int v = (i < N_NODES) ? DEG_IN[i] : 0;
    if (i < N_NODES) {
        g_norm_out[i] = rsqrtf(fmaxf((float)DEG_OUT[i], 1.0f));
        g_norm_in[i]  = rsqrtf(fmaxf((float)v, 1.0f));
    }
    sm[tid] = v;
    __syncthreads();
    for (int ofs = 1; ofs < SCAN_T; ofs <<= 1) {
        int t = (tid >= ofs) ? sm[tid - ofs] : 0;
        __syncthreads();
        sm[tid] += t;
        __syncthreads();
    }

    if (tid == 0) {
        int total = sm[SCAN_T - 1];
        g_scan_agg[b] = total;
        __threadfence();
        atomicExch(&SFLAG[b], 1);

        int p = 0;
        for (int j = b - 1; j >= 0; --j) {
            int f;
            do { f = atomicAdd(&SFLAG[j], 0); } while (f == 0);
            __threadfence();
            if (f == 2) { p += g_scan_pref[j]; break; }
            p += g_scan_agg[j];
        }
        g_scan_pref[b] = p + total;
        __threadfence();
        atomicExch(&SFLAG[b], 2);
        s_prefix = p;
    }
    __syncthreads();

    if (i < N_NODES) g_off[i + 1] = sm[tid] + s_prefix;
    if (i == 0) g_off[0] = 0;
}

// ---------------------------------------------------------------------------
// K3: fused — CSR fill + W1 transpose fp16 + Wcomb/bcomb
#define FILL_B  ((N_EDGES + 255) / 256)        // 6250
#define W1T_B   ((HDIM * HDIM) / 256)          // 64
#define WC_B    (HDIM + 1)                     // 129
#define K3_GRID (FILL_B + W1T_B + WC_B)

__global__ void __launch_bounds__(256)
fill_prep_kernel(const int* __restrict__ src, const int* __restrict__ dst,
                 const float* __restrict__ W1,
                 const float* __restrict__ W2, const float* __restrict__ Wfc,
                 const float* __restrict__ b2, const float* __restrict__ bfc) {
    const int bid = blockIdx.x;
    const int tid = threadIdx.x;

    if (bid < FILL_B) {
        int e = bid * 256 + tid;
        if (e < N_EDGES) {
            int d = dst[e];
            int pos = g_off[d] + atomicAdd(&CURSOR[d], 1);
            g_csr_src[pos] = src[e];
        }
    } else if (bid < FILL_B + W1T_B) {
        int idx = (bid - FILL_B) * 256 + tid;            // over 16384 elems
        int k = idx >> 7;
        int n = idx & 127;
        g_w1ht[n * HDIM + k] = __float2half_rn(W1[k * HDIM + n]);
    } else {
        int j = bid - FILL_B - W1T_B;                    // 0..128
        __shared__ float row[HDIM];
        const float* srcrow = (j < HDIM) ? (W2 + j * HDIM) : b2;
        if (tid < HDIM) row[tid] = srcrow[tid];
        __syncthreads();
        if (tid < CDIM) {
            float acc = (j < HDIM) ? 0.f : bfc[tid];
#pragma unroll 8
            for (int k = 0; k < HDIM; k++)
                acc = fmaf(row[k], Wfc[k * CDIM + tid], acc);
            if (j < HDIM) g_wcomb[j * CDIM + tid] = acc;
            else          g_bcomb[tid] = acc;
        }
    }
}

// ---------------------------------------------------------------------------
// K4 (PROFILED SLOT): gather1:
//   a1h[n,:] = fp16( norm_in[n] * sum_{s in N_in(n)} x[s,:] * norm_out[s] )
// reads fp32 x directly; norm_out fused per-edge (no conversion pass needed)
__global__ void __launch_bounds__(256)
gather1_kernel(const float* __restrict__ x) {
    int t    = blockIdx.x * blockDim.x + threadIdx.x;
    int node = t >> 5;
    int lane = t & 31;
    if (node >= N_NODES) return;

    int beg = g_off[node];
    int end = g_off[node + 1];
    const float4* in4 = (const float4*)x;

    float4 acc = make_float4(0.f, 0.f, 0.f, 0.f);
    int i = beg;
    for (; i + 4 <= end; i += 4) {
        int s0 = g_csr_src[i + 0];
        int s1 = g_csr_src[i + 1];
        int s2 = g_csr_src[i + 2];
        int s3 = g_csr_src[i + 3];
        float n0 = g_norm_out[s0];
        float n1 = g_norm_out[s1];
        float n2 = g_norm_out[s2];
        float n3 = g_norm_out[s3];
        float4 v0 = __ldg(in4 + (size_t)s0 * 32 + lane);
        float4 v1 = __ldg(in4 + (size_t)s1 * 32 + lane);
        float4 v2 = __ldg(in4 + (size_t)s2 * 32 + lane);
        float4 v3 = __ldg(in4 + (size_t)s3 * 32 + lane);
        acc.x = fmaf(v0.x, n0, fmaf(v1.x, n1, fmaf(v2.x, n2, fmaf(v3.x, n3, acc.x))));
        acc.y = fmaf(v0.y, n0, fmaf(v1.y, n1, fmaf(v2.y, n2, fmaf(v3.y, n3, acc.y))));
        acc.z = fmaf(v0.z, n0, fmaf(v1.z, n1, fmaf(v2.z, n2, fmaf(v3.z, n3, acc.z))));
        acc.w = fmaf(v0.w, n0, fmaf(v1.w, n1, fmaf(v2.w, n2, fmaf(v3.w, n3, acc.w))));
    }
    for (; i < end; i++) {
        int s = g_csr_src[i];
        float ns = g_norm_out[s];
        float4 v = __ldg(in4 + (size_t)s * 32 + lane);
        acc.x = fmaf(v.x, ns, acc.x); acc.y = fmaf(v.y, ns, acc.y);
        acc.z = fmaf(v.z, ns, acc.z); acc.w = fmaf(v.w, ns, acc.w);
    }

    float ni = g_norm_in[node];
    __half2 p0 = __floats2half2_rn(acc.x * ni, acc.y * ni);
    __half2 p1 = __floats2half2_rn(acc.z * ni, acc.w * ni);
    uint2 w;
    w.x = *reinterpret_cast<unsigned*>(&p0);
    w.y = *reinterpret_cast<unsigned*>(&p1);
    ((uint2*)g_a1h)[(size_t)node * 32 + lane] = w;
}

// ---------------------------------------------------------------------------
// K5: HMMA GEMM: h1h[n,:] = fp16( relu(a1h[n,:] @ W1 + b1) * norm_out[n] )
#define APAD 136
#define GEMM_SMEM (2 * HDIM * APAD * (int)sizeof(__half))

__global__ void __launch_bounds__(256)
gemm_hmma_kernel(const float* __restrict__ bias) {
    extern __shared__ __half smem[];
    __half* As = smem;                    // [128][APAD]
    __half* Ws = smem + HDIM * APAD;      // [128][APAD]  (W1^T: [n][k])
    __shared__ float bs[HDIM];

    const int tid = threadIdx.x;
    const int block_row = blockIdx.x * 128;

    if (tid < HDIM) bs[tid] = bias[tid];

#pragma unroll
    for (int t = 0; t < 8; t++) {
        int idx = tid + t * 256;
        int r   = idx >> 4;
        int c8  = (idx & 15) << 3;
        int n   = block_row + r;
        uint4 v = make_uint4(0u, 0u, 0u, 0u);
        if (n < N_NODES) v = *(const uint4*)(g_a1h + (size_t)n * HDIM + c8);
        *(uint4*)(As + r * APAD + c8) = v;
        uint4 wv = *(const uint4*)(g_w1ht + r * HDIM + c8);
        *(uint4*)(Ws + r * APAD + c8) = wv;
    }
    __syncthreads();

    const int warp  = tid >> 5;
    const int lane  = tid & 31;
    const int warpM = warp & 3;
    const int warpN = warp >> 2;
    const int lr    = lane >> 2;
    const int lc    = (lane & 3) << 1;

    float acc[2][8][4];
#pragma unroll
    for (int m = 0; m < 2; m++)
#pragma unroll
        for (int n = 0; n < 8; n++)
#pragma unroll
            for (int q = 0; q < 4; q++) acc[m][n][q] = 0.f;

#pragma unroll
    for (int k16 = 0; k16 < 8; k16++) {
        const int kb = k16 * 16 + lc;
        unsigned a[2][4];
#pragma unroll
        for (int m = 0; m < 2; m++) {
            const __half* ap = As + (warpM * 32 + m * 16 + lr) * APAD;
            a[m][0] = *(const unsigned*)(ap + kb);
            a[m][1] = *(const unsigned*)(ap + 8 * APAD + kb);
            a[m][2] = *(const unsigned*)(ap + kb + 8);
            a[m][3] = *(const unsigned*)(ap + 8 * APAD + kb + 8);
        }
#pragma unroll
        for (int n = 0; n < 8; n++) {
            const __half* bp = Ws + (warpN * 64 + n * 8 + lr) * APAD + kb;
            unsigned b0 = *(const unsigned*)(bp);
            unsigned b1 = *(const unsigned*)(bp + 8);
#pragma unroll
            for (int m = 0; m < 2; m++) {
                asm volatile(
                    "mma.sync.aligned.m16n8k16.row.col.f32.f16.f16.f32 "
                    "{%0,%1,%2,%3}, {%4,%5,%6,%7}, {%8,%9}, {%0,%1,%2,%3};"
                    : "+f"(acc[m][n][0]), "+f"(acc[m][n][1]),
                      "+f"(acc[m][n][2]), "+f"(acc[m][n][3])
                    : "r"(a[m][0]), "r"(a[m][1]), "r"(a[m][2]), "r"(a[m][3]),
                      "r"(b0), "r"(b1));
            }
        }
    }

#pragma unroll
    for (int m = 0; m < 2; m++) {
        int r0 = block_row + warpM * 32 + m * 16 + lr;
        int r1 = r0 + 8;
        float no0 = (r0 < N_NODES) ? g_norm_out[r0] : 0.f;
        float no1 = (r1 < N_NODES) ? g_norm_out[r1] : 0.f;
#pragma unroll
        for (int n = 0; n < 8; n++) {
            int col = warpN * 64 + n * 8 + lc;
            float bb0 = bs[col], bb1 = bs[col + 1];
            if (r0 < N_NODES) {
                __half2 h = __floats2half2_rn(fmaxf(acc[m][n][0] + bb0, 0.f) * no0,
                                              fmaxf(acc[m][n][1] + bb1, 0.f) * no0);
                *(__half2*)(g_h1h + (size_t)r0 * HDIM + col) = h;
            }
            if (r1 < N_NODES) {
                __half2 h = __floats2half2_rn(fmaxf(acc[m][n][2] + bb0, 0.f) * no1,
                                              fmaxf(acc[m][n][3] + bb1, 0.f) * no1);
                *(__half2*)(g_h1h + (size_t)r1 * HDIM + col) = h;
            }
        }
    }
}

// ---------------------------------------------------------------------------
// helper: accumulate one fp16 row (4 halves per lane) into float4
__device__ __forceinline__ void acc_half_row(const uint2* __restrict__ base,
                                             int s, int lane, float4& acc) {
    uint2 r = __ldg(base + (size_t)s * 32 + lane);
    __half2 h0 = *reinterpret_cast<__half2*>(&r.x);
    __half2 h1 = *reinterpret_cast<__half2*>(&r.y);
    float2 f0 = __half22float2(h0);
    float2 f1 = __half22float2(h1);
    acc.x += f0.x; acc.y += f0.y; acc.z += f1.x; acc.w += f1.y;
}

// K6: fused gather2 + FC (512 threads, 16 nodes/block -> Wcomb amortized):
//   out[n, c] = (sum_{s} h1h[s,:]) * norm_in[n] @ Wcomb[:,c] + bcomb[c]
__global__ void __launch_bounds__(512)
gather2_fc_kernel(float* __restrict__ out) {
    __shared__ float sm[16][HDIM + 4];
    __shared__ float Ws[HDIM * CDIM];
    __shared__ float bsh[CDIM];

    const int tid  = threadIdx.x;
    const int wid  = tid >> 5;
    const int lane = tid & 31;
    const int node = blockIdx.x * 16 + wid;

    for (int i = tid; i < HDIM * CDIM; i += 512) Ws[i] = g_wcomb[i];
    if (tid < CDIM) bsh[tid] = g_bcomb[tid];

    if (node < N_NODES) {
        int beg = g_off[node];
        int end = g_off[node + 1];
        const uint2* in = (const uint2*)g_h1h;

        float4 acc = make_float4(0.f, 0.f, 0.f, 0.f);
        int i = beg;
        for (; i + 8 <= end; i += 8) {
#pragma unroll
            for (int u = 0; u < 8; u++) acc_half_row(in, g_csr_src[i + u], lane, acc);
        }
        for (; i < end; i++) acc_half_row(in, g_csr_src[i], lane, acc);

        float ni = g_norm_in[node];
        acc.x *= ni; acc.y *= ni; acc.z *= ni; acc.w *= ni;
        *(float4*)&sm[wid][lane * 4] = acc;
    }
    __syncthreads();

    if (node < N_NODES) {
        float a0 = 0.f, a1 = 0.f;
        const int c0 = lane;
        const int c1 = 32 + lane;
#pragma unroll 8
        for (int j = 0; j < HDIM; j++) {
            float xv = sm[wid][j];
            a0 = fmaf(xv, Ws[j * CDIM + c0], a0);
            if (lane < 8) a1 = fmaf(xv, Ws[j * CDIM + c1], a1);
        }
        out[(size_t)node * CDIM + c0] = a0 + bsh[c0];
        if (lane < 8) out[(size_t)node * CDIM + c1] = a1 + bsh[c1];
    }
}

// ---------------------------------------------------------------------------
extern "C" void kernel_launch(void* const* d_in, const int* in_sizes, int n_in,
                              void* d_out, int out_size) {
    const float* x   = (const float*)d_in[0];
    const int*   ei  = (const int*)  d_in[1];
    const float* W1  = (const float*)d_in[2];
    const float* b1  = (const float*)d_in[3];
    const float* W2  = (const float*)d_in[4];
    const float* b2  = (const float*)d_in[5];
    const float* Wfc = (const float*)d_in[6];
    const float* bfc = (const float*)d_in[7];
    float* out = (float*)d_out;

    const int* src = ei;            // edge_index row 0
    const int* dst = ei + N_EDGES;  // edge_index row 1

    int* p_ints;
    cudaGetSymbolAddress((void**)&p_ints, g_ints);

    static bool attr_set = false;
    if (!attr_set) {
        cudaFuncSetAttribute(gemm_hmma_kernel,
                             cudaFuncAttributeMaxDynamicSharedMemorySize, GEMM_SMEM);
        attr_set = true;
    }

    const int agg_blocks = (N_NODES * 32 + 255) / 256;   // 12500

    // zero [deg_out | deg_in | cursor | scan flags]
    cudaMemsetAsync(p_ints, 0, (3 * N_NODES + 128) * sizeof(int));
    // K1: degrees
    deg_kernel<<<(N_EDGES + 255) / 256, 256>>>(src, dst);
    // K2: lookback scan + norms
    scan_norm_kernel<<<SCAN_BLOCKS, SCAN_T>>>();
    // K3: CSR fill + W1^T fp16 + Wcomb/bcomb
    fill_prep_kernel<<<K3_GRID, 256>>>(src, dst, W1, W2, Wfc, b2, bfc);
    // K4 (profiled): gather1 (fp32 x, fused norms) -> a1h fp16
    gather1_kernel<<<agg_blocks, 256>>>(x);
    // K5: tensor-core GEMM -> h1h fp16
    gemm_hmma_kernel<<<(N_NODES + 127) / 128, 256, GEMM_SMEM>>>(b1);
    // K6: fused gather2 + FC (16 nodes/block)
    gather2_fc_kernel<<<(N_NODES + 15) / 16, 512>>>(out);
}

// round 7
// speedup vs baseline: 1.5227x; 1.1462x over previous
#include <cuda_runtime.h>
#include <cuda_fp16.h>
#include <cstddef>

#define N_NODES 100000
#define N_EDGES 1600000
#define HDIM 128
#define CDIM 40

#define SCAN_T 1024
#define SCAN_BLOCKS ((N_NODES + SCAN_T - 1) / SCAN_T)   // 98

// ---- device scratch (allocation-free rule) ----
__device__ float  g_norm_out[N_NODES];
__device__ float  g_norm_in[N_NODES];
__device__ int    g_ints[3 * N_NODES + 128];   // [deg_out | deg_in | cursor | scan flags]
__device__ int    g_off[N_NODES + 1];
__device__ int    g_csr_src[N_EDGES];
__device__ int    g_scan_agg[SCAN_BLOCKS];
__device__ int    g_scan_pref[SCAN_BLOCKS];
__device__ float  g_bcomb[CDIM];
__device__ __half g_w1ht[HDIM * HDIM];             // W1^T fp16: [n][k]
__device__ __half g_wcombh[CDIM * HDIM];           // Wcomb^T fp16: [c][k]
__device__ __half g_xh[(size_t)N_NODES * HDIM];    // raw x, fp16
__device__ __half g_h1h[(size_t)N_NODES * HDIM];   // relu(...)*norm_out, fp16

#define DEG_OUT (g_ints)
#define DEG_IN  (g_ints + N_NODES)
#define CURSOR  (g_ints + 2 * N_NODES)
#define SFLAG   (g_ints + 3 * N_NODES)

#define APAD 136   // halves per smem row

// ---------------------------------------------------------------------------
// K1: degree histogram + raw x -> fp16 cast (independent work, one kernel)
#define DEGB  ((N_EDGES + 255) / 256)          // 6250
#define CONVB ((N_NODES * 32 + 255) / 256)     // 12500
#define K1_GRID (DEGB + CONVB)

__global__ void __launch_bounds__(256)
deg_conv_kernel(const int* __restrict__ src, const int* __restrict__ dst,
                const float* __restrict__ x) {
    const int bid = blockIdx.x;
    const int tid = threadIdx.x;
    if (bid < DEGB) {
        int e = bid * 256 + tid;
        if (e < N_EDGES) {
            atomicAdd(&DEG_OUT[src[e]], 1);
            atomicAdd(&DEG_IN[dst[e]], 1);
        }
    } else {
        int t = (bid - DEGB) * 256 + tid;
        int node = t >> 5;
        int lane = t & 31;
        if (node < N_NODES) {
            float4 v = __ldg((const float4*)x + (size_t)node * 32 + lane);
            __half2 p0 = __floats2half2_rn(v.x, v.y);
            __half2 p1 = __floats2half2_rn(v.z, v.w);
            uint2 w;
            w.x = *reinterpret_cast<unsigned*>(&p0);
            w.y = *reinterpret_cast<unsigned*>(&p1);
            ((uint2*)g_xh)[(size_t)node * 32 + lane] = w;
        }
    }
}

// ---------------------------------------------------------------------------
// K2: single-pass decoupled-lookback scan of deg_in -> g_off, plus norms.
__global__ void __launch_bounds__(SCAN_T)
scan_norm_kernel() {
    __shared__ int sm[SCAN_T];
    __shared__ int s_prefix;
    const int b = blockIdx.x;
    const int tid = threadIdx.x;
    const int i = b * SCAN_T + tid;

    int v = (i < N_NODES) ? DEG_IN[i] : 0;
    if (i < N_NODES) {
        g_norm_out[i] = rsqrtf(fmaxf((float)DEG_OUT[i], 1.0f));
        g_norm_in[i]  = rsqrtf(fmaxf((float)v, 1.0f));
    }
    sm[tid] = v;
    __syncthreads();
    for (int ofs = 1; ofs < SCAN_T; ofs <<= 1) {
        int t = (tid >= ofs) ? sm[tid - ofs] : 0;
        __syncthreads();
        sm[tid] += t;
        __syncthreads();
    }

    if (tid == 0) {
        int total = sm[SCAN_T - 1];
        g_scan_agg[b] = total;
        __threadfence();
        atomicExch(&SFLAG[b], 1);

        int p = 0;
        for (int j = b - 1; j >= 0; --j) {
            int f;
            do { f = atomicAdd(&SFLAG[j], 0); } while (f == 0);
            __threadfence();
            if (f == 2) { p += g_scan_pref[j]; break; }
            p += g_scan_agg[j];
        }
        g_scan_pref[b] = p + total;
        __threadfence();
        atomicExch(&SFLAG[b], 2);
        s_prefix = p;
    }
    __syncthreads();

    if (i < N_NODES) g_off[i + 1] = sm[tid] + s_prefix;
    if (i == 0) g_off[0] = 0;
}

// ---------------------------------------------------------------------------
// K3: fused — CSR fill + W1^T fp16 + Wcomb^T fp16 + bcomb
#define FILL_B  ((N_EDGES + 255) / 256)        // 6250
#define W1T_B   ((HDIM * HDIM) / 256)          // 64
#define WC_B    (HDIM + 1)                     // 129
#define K3_GRID (FILL_B + W1T_B + WC_B)

__global__ void __launch_bounds__(256)
fill_prep_kernel(const int* __restrict__ src, const int* __restrict__ dst,
                 const float* __restrict__ W1,
                 const float* __restrict__ W2, const float* __restrict__ Wfc,
                 const float* __restrict__ b2, const float* __restrict__ bfc) {
    const int bid = blockIdx.x;
    const int tid = threadIdx.x;

    if (bid < FILL_B) {
        int e = bid * 256 + tid;
        if (e < N_EDGES) {
            int d = dst[e];
            int pos = g_off[d] + atomicAdd(&CURSOR[d], 1);
            g_csr_src[pos] = src[e];
        }
    } else if (bid < FILL_B + W1T_B) {
        int idx = (bid - FILL_B) * 256 + tid;            // over 16384 elems
        int k = idx >> 7;
        int n = idx & 127;
        g_w1ht[n * HDIM + k] = __float2half_rn(W1[k * HDIM + n]);
    } else {
        int j = bid - FILL_B - W1T_B;                    // 0..128; j<128: row j of W2
        __shared__ float row[HDIM];
        const float* srcrow = (j < HDIM) ? (W2 + j * HDIM) : b2;
        if (tid < HDIM) row[tid] = srcrow[tid];
        __syncthreads();
        if (tid < CDIM) {
            float acc = (j < HDIM) ? 0.f : bfc[tid];
#pragma unroll 8
            for (int k = 0; k < HDIM; k++)
                acc = fmaf(row[k], Wfc[k * CDIM + tid], acc);
            if (j < HDIM) g_wcombh[tid * HDIM + j] = __float2half_rn(acc);
            else          g_bcomb[tid] = acc;
        }
    }
}

// ---------------------------------------------------------------------------
// fp16-row accumulate helpers
__device__ __forceinline__ void acc_half_row(const uint2* __restrict__ base,
                                             int s, int lane, float4& acc) {
    uint2 r = __ldg(base + (size_t)s * 32 + lane);
    __half2 h0 = *reinterpret_cast<__half2*>(&r.x);
    __half2 h1 = *reinterpret_cast<__half2*>(&r.y);
    float2 f0 = __half22float2(h0);
    float2 f1 = __half22float2(h1);
    acc.x += f0.x; acc.y += f0.y; acc.z += f1.x; acc.w += f1.y;
}

__device__ __forceinline__ void acc_half_row_scaled(const uint2* __restrict__ base,
                                                    int s, float sc, int lane, float4& acc) {
    uint2 r = __ldg(base + (size_t)s * 32 + lane);
    __half2 h0 = *reinterpret_cast<__half2*>(&r.x);
    __half2 h1 = *reinterpret_cast<__half2*>(&r.y);
    float2 f0 = __half22float2(h0);
    float2 f1 = __half22float2(h1);
    acc.x = fmaf(f0.x, sc, acc.x); acc.y = fmaf(f0.y, sc, acc.y);
    acc.z = fmaf(f1.x, sc, acc.z); acc.w = fmaf(f1.y, sc, acc.w);
}

// ---------------------------------------------------------------------------
// K4 (PROFILED): fused gather1 + HMMA GEMM.
//   A row n = norm_in[n] * sum_{s in N_in(n)} xh[s,:] * norm_out[s]   (built in smem)
//   h1h[n,:] = fp16( relu(A[n,:] @ W1 + b1) * norm_out[n] )
#define GEMM_SMEM (2 * HDIM * APAD * (int)sizeof(__half))   // 69632 B

__global__ void __launch_bounds__(256)
gemm_fused_kernel(const float* __restrict__ bias) {
    extern __shared__ __half smem[];
    __half* As = smem;                    // [128][APAD]
    __half* Ws = smem + HDIM * APAD;      // [128][APAD]  (W1^T: [n][k])
    __shared__ float bs[HDIM];

    const int tid  = threadIdx.x;
    const int warp = tid >> 5;
    const int lane = tid & 31;
    const int block_row = blockIdx.x * 128;

    if (tid < HDIM) bs[tid] = bias[tid];

    // stage W1^T tile
#pragma unroll
    for (int t = 0; t < 8; t++) {
        int idx = tid + t * 256;          // 2048 uint4
        int r   = idx >> 4;
        int c8  = (idx & 15) << 3;
        *(uint4*)(Ws + r * APAD + c8) = *(const uint4*)(g_w1ht + r * HDIM + c8);
    }

    // gather phase: warp w builds rows w*16 .. w*16+15 of As
    const uint2* xin = (const uint2*)g_xh;
#pragma unroll 1
    for (int i = 0; i < 16; i++) {
        int r = warp * 16 + i;
        int n = block_row + r;
        uint2 w = make_uint2(0u, 0u);
        if (n < N_NODES) {
            int beg = g_off[n];
            int end = g_off[n + 1];
            float4 acc = make_float4(0.f, 0.f, 0.f, 0.f);
            int j = beg;
            for (; j + 4 <= end; j += 4) {
                int s0 = g_csr_src[j + 0];
                int s1 = g_csr_src[j + 1];
                int s2 = g_csr_src[j + 2];
                int s3 = g_csr_src[j + 3];
                acc_half_row_scaled(xin, s0, g_norm_out[s0], lane, acc);
                acc_half_row_scaled(xin, s1, g_norm_out[s1], lane, acc);
                acc_half_row_scaled(xin, s2, g_norm_out[s2], lane, acc);
                acc_half_row_scaled(xin, s3, g_norm_out[s3], lane, acc);
            }
            for (; j < end; j++) {
                int s = g_csr_src[j];
                acc_half_row_scaled(xin, s, g_norm_out[s], lane, acc);
            }
            float ni = g_norm_in[n];
            __half2 p0 = __floats2half2_rn(acc.x * ni, acc.y * ni);
            __half2 p1 = __floats2half2_rn(acc.z * ni, acc.w * ni);
            w.x = *reinterpret_cast<unsigned*>(&p0);
            w.y = *reinterpret_cast<unsigned*>(&p1);
        }
        *(uint2*)(As + r * APAD + lane * 4) = w;
    }
    __syncthreads();

    // MMA phase: 8 warps = 4 M-groups x 2 N-groups, warp tile 32x64
    const int warpM = warp & 3;
    const int warpN = warp >> 2;
    const int lr    = lane >> 2;
    const int lc    = (lane & 3) << 1;

    float acc[2][8][4];
#pragma unroll
    for (int m = 0; m < 2; m++)
#pragma unroll
        for (int n = 0; n < 8; n++)
#pragma unroll
            for (int q = 0; q < 4; q++) acc[m][n][q] = 0.f;

#pragma unroll
    for (int k16 = 0; k16 < 8; k16++) {
        const int kb = k16 * 16 + lc;
        unsigned a[2][4];
#pragma unroll
        for (int m = 0; m < 2; m++) {
            const __half* ap = As + (warpM * 32 + m * 16 + lr) * APAD;
            a[m][0] = *(const unsigned*)(ap + kb);
            a[m][1] = *(const unsigned*)(ap + 8 * APAD + kb);
            a[m][2] = *(const unsigned*)(ap + kb + 8);
            a[m][3] = *(const unsigned*)(ap + 8 * APAD + kb + 8);
        }
#pragma unroll
        for (int n = 0; n < 8; n++) {
            const __half* bp = Ws + (warpN * 64 + n * 8 + lr) * APAD + kb;
            unsigned b0 = *(const unsigned*)(bp);
            unsigned b1 = *(const unsigned*)(bp + 8);
#pragma unroll
            for (int m = 0; m < 2; m++) {
                asm volatile(
                    "mma.sync.aligned.m16n8k16.row.col.f32.f16.f16.f32 "
                    "{%0,%1,%2,%3}, {%4,%5,%6,%7}, {%8,%9}, {%0,%1,%2,%3};"
                    : "+f"(acc[m][n][0]), "+f"(acc[m][n][1]),
                      "+f"(acc[m][n][2]), "+f"(acc[m][n][3])
                    : "r"(a[m][0]), "r"(a[m][1]), "r"(a[m][2]), "r"(a[m][3]),
                      "r"(b0), "r"(b1));
            }
        }
    }

#pragma unroll
    for (int m = 0; m < 2; m++) {
        int r0 = block_row + warpM * 32 + m * 16 + lr;
        int r1 = r0 + 8;
        float no0 = (r0 < N_NODES) ? g_norm_out[r0] : 0.f;
        float no1 = (r1 < N_NODES) ? g_norm_out[r1] : 0.f;
#pragma unroll
        for (int n = 0; n < 8; n++) {
            int col = warpN * 64 + n * 8 + lc;
            float bb0 = bs[col], bb1 = bs[col + 1];
            if (r0 < N_NODES) {
                __half2 h = __floats2half2_rn(fmaxf(acc[m][n][0] + bb0, 0.f) * no0,
                                              fmaxf(acc[m][n][1] + bb1, 0.f) * no0);
                *(__half2*)(g_h1h + (size_t)r0 * HDIM + col) = h;
            }
            if (r1 < N_NODES) {
                __half2 h = __floats2half2_rn(fmaxf(acc[m][n][2] + bb0, 0.f) * no1,
                                              fmaxf(acc[m][n][3] + bb1, 0.f) * no1);
                *(__half2*)(g_h1h + (size_t)r1 * HDIM + col) = h;
            }
        }
    }
}

// ---------------------------------------------------------------------------
// K5: fused gather2 + FC via HMMA.
//   A row n = norm_in[n] * sum_{s} h1h[s,:]  (fp16 in smem)
//   out[n, 0:40] = A[n,:] @ Wcomb + bcomb   (N=40 = 5 n-frags exactly)
__global__ void __launch_bounds__(256)
gather2_fc_kernel(float* __restrict__ out) {
    __shared__ __half As[HDIM * APAD];    // [128][APAD]
    __shared__ __half Wc[CDIM * APAD];    // [40][APAD]   (Wcomb^T: [c][k])
    __shared__ float bsh[CDIM];

    const int tid  = threadIdx.x;
    const int warp = tid >> 5;
    const int lane = tid & 31;
    const int block_row = blockIdx.x * 128;

    if (tid < CDIM) bsh[tid] = g_bcomb[tid];

    // stage Wcomb^T (40 x 128 halves = 640 uint4)
    for (int idx = tid; idx < (CDIM * HDIM) / 8; idx += 256) {
        int r  = idx >> 4;
        int c8 = (idx & 15) << 3;
        *(uint4*)(Wc + r * APAD + c8) = ((const uint4*)g_wcombh)[idx];
    }

    // gather phase
    const uint2* hin = (const uint2*)g_h1h;
#pragma unroll 1
    for (int i = 0; i < 16; i++) {
        int r = warp * 16 + i;
        int n = block_row + r;
        uint2 w = make_uint2(0u, 0u);
        if (n < N_NODES) {
            int beg = g_off[n];
            int end = g_off[n + 1];
            float4 acc = make_float4(0.f, 0.f, 0.f, 0.f);
            int j = beg;
            for (; j + 8 <= end; j += 8) {
#pragma unroll
                for (int u = 0; u < 8; u++) acc_half_row(hin, g_csr_src[j + u], lane, acc);
            }
            for (; j < end; j++) acc_half_row(hin, g_csr_src[j], lane, acc);
            float ni = g_norm_in[n];
            __half2 p0 = __floats2half2_rn(acc.x * ni, acc.y * ni);
            __half2 p1 = __floats2half2_rn(acc.z * ni, acc.w * ni);
            w.x = *reinterpret_cast<unsigned*>(&p0);
            w.y = *reinterpret_cast<unsigned*>(&p1);
        }
        *(uint2*)(As + r * APAD + lane * 4) = w;
    }
    __syncthreads();

    // MMA: warp handles 16 rows (M), all 40 cols (5 n-frags)
    const int lr = lane >> 2;
    const int lc = (lane & 3) << 1;

    float acc[5][4];
#pragma unroll
    for (int n = 0; n < 5; n++)
#pragma unroll
        for (int q = 0; q < 4; q++) acc[n][q] = 0.f;

#pragma unroll
    for (int k16 = 0; k16 < 8; k16++) {
        const int kb = k16 * 16 + lc;
        const __half* ap = As + (warp * 16 + lr) * APAD;
        unsigned a0 = *(const unsigned*)(ap + kb);
        unsigned a1 = *(const unsigned*)(ap + 8 * APAD + kb);
        unsigned a2 = *(const unsigned*)(ap + kb + 8);
        unsigned a3 = *(const unsigned*)(ap + 8 * APAD + kb + 8);
#pragma unroll
        for (int n = 0; n < 5; n++) {
            const __half* bp = Wc + (n * 8 + lr) * APAD + kb;
            unsigned b0 = *(const unsigned*)(bp);
            unsigned b1 = *(const unsigned*)(bp + 8);
            asm volatile(
                "mma.sync.aligned.m16n8k16.row.col.f32.f16.f16.f32 "
                "{%0,%1,%2,%3}, {%4,%5,%6,%7}, {%8,%9}, {%0,%1,%2,%3};"
                : "+f"(acc[n][0]), "+f"(acc[n][1]), "+f"(acc[n][2]), "+f"(acc[n][3])
                : "r"(a0), "r"(a1), "r"(a2), "r"(a3), "r"(b0), "r"(b1));
        }
    }

    // epilogue: +bcomb, write fp32 out[n*40 + c]
    int r0 = block_row + warp * 16 + lr;
    int r1 = r0 + 8;
#pragma unroll
    for (int n = 0; n < 5; n++) {
        int col = n * 8 + lc;
        float b0 = bsh[col], b1 = bsh[col + 1];
        if (r0 < N_NODES) {
            float2 v = make_float2(acc[n][0] + b0, acc[n][1] + b1);
            *(float2*)(out + (size_t)r0 * CDIM + col) = v;
        }
        if (r1 < N_NODES) {
            float2 v = make_float2(acc[n][2] + b0, acc[n][3] + b1);
            *(float2*)(out + (size_t)r1 * CDIM + col) = v;
        }
    }
}

// ---------------------------------------------------------------------------
extern "C" void kernel_launch(void* const* d_in, const int* in_sizes, int n_in,
                              void* d_out, int out_size) {
    const float* x   = (const float*)d_in[0];
    const int*   ei  = (const int*)  d_in[1];
    const float* W1  = (const float*)d_in[2];
    const float* b1  = (const float*)d_in[3];
    const float* W2  = (const float*)d_in[4];
    const float* b2  = (const float*)d_in[5];
    const float* Wfc = (const float*)d_in[6];
    const float* bfc = (const float*)d_in[7];
    float* out = (float*)d_out;

    const int* src = ei;            // edge_index row 0
    const int* dst = ei + N_EDGES;  // edge_index row 1

    int* p_ints;
    cudaGetSymbolAddress((void**)&p_ints, g_ints);

    static bool attr_set = false;
    if (!attr_set) {
        cudaFuncSetAttribute(gemm_fused_kernel,
                             cudaFuncAttributeMaxDynamicSharedMemorySize, GEMM_SMEM);
        attr_set = true;
    }

    const int node_blocks = (N_NODES + 127) / 128;   // 782

    // zero [deg_out | deg_in | cursor | scan flags]
    cudaMemsetAsync(p_ints, 0, (3 * N_NODES + 128) * sizeof(int));
    // K1: degrees + x->fp16 cast
    deg_conv_kernel<<<K1_GRID, 256>>>(src, dst, x);
    // K2: lookback scan + norms
    scan_norm_kernel<<<SCAN_BLOCKS, SCAN_T>>>();
    // K3: CSR fill + W1^T fp16 + Wcomb^T fp16 + bcomb
    fill_prep_kernel<<<K3_GRID, 256>>>(src, dst, W1, W2, Wfc, b2, bfc);
    // K4 (profiled): fused gather1 + HMMA GEMM -> h1h
    gemm_fused_kernel<<<node_blocks, 256, GEMM_SMEM>>>(b1);
    // K5: fused gather2 + FC (HMMA) -> out
    gather2_fc_kernel<<<node_blocks, 256>>>(out);
}

// round 8
// speedup vs baseline: 2.0959x; 1.3765x over previous
#include <cuda_runtime.h>
#include <cuda_fp16.h>
#include <cstddef>

#define N_NODES 100000
#define N_EDGES 1600000
#define HDIM 128
#define CDIM 40

#define SCAN_T 1024
#define SCAN_BLOCKS ((N_NODES + SCAN_T - 1) / SCAN_T)   // 98

// ---- device scratch (allocation-free rule) ----
__device__ float  g_norm_out[N_NODES];
__device__ float  g_norm_in[N_NODES];
__device__ int    g_ints[3 * N_NODES + 128];   // [deg_out | deg_in | cursor | scan flags]
__device__ int    g_off[N_NODES + 1];
__device__ int    g_csr_src[N_EDGES];
__device__ int    g_scan_agg[SCAN_BLOCKS];
__device__ int    g_scan_pref[SCAN_BLOCKS];
__device__ float  g_bcomb[CDIM];
__device__ __half g_w1ht[HDIM * HDIM];             // W1^T fp16: [n][k]
__device__ __half g_wcombh[CDIM * HDIM];           // Wcomb^T fp16: [c][k]
__device__ __half g_xh[(size_t)N_NODES * HDIM];    // raw x fp16; later reused as a2h
__device__ __half g_a1h[(size_t)N_NODES * HDIM];   // gather1 * norm_in, fp16
__device__ __half g_h1h[(size_t)N_NODES * HDIM];   // relu(...)*norm_out, fp16

#define DEG_OUT (g_ints)
#define DEG_IN  (g_ints + N_NODES)
#define CURSOR  (g_ints + 2 * N_NODES)
#define SFLAG   (g_ints + 3 * N_NODES)

#define APAD 136   // halves per smem row (uint4-aligned, conflict-free frags)

// ---------------------------------------------------------------------------
// K1: degree histogram + raw x -> fp16 cast (independent work, one kernel)
#define DEGB  ((N_EDGES + 255) / 256)          // 6250
#define CONVB ((N_NODES * 32 + 255) / 256)     // 12500
#define K1_GRID (DEGB + CONVB)

__global__ void __launch_bounds__(256)
deg_conv_kernel(const int* __restrict__ src, const int* __restrict__ dst,
                const float* __restrict__ x) {
    const int bid = blockIdx.x;
    const int tid = threadIdx.x;
    if (bid < DEGB) {
        int e = bid * 256 + tid;
        if (e < N_EDGES) {
            atomicAdd(&DEG_OUT[src[e]], 1);
            atomicAdd(&DEG_IN[dst[e]], 1);
        }
    } else {
        int t = (bid - DEGB) * 256 + tid;
        int node = t >> 5;
        int lane = t & 31;
        if (node < N_NODES) {
            float4 v = __ldg((const float4*)x + (size_t)node * 32 + lane);
            __half2 p0 = __floats2half2_rn(v.x, v.y);
            __half2 p1 = __floats2half2_rn(v.z, v.w);
            uint2 w;
            w.x = *reinterpret_cast<unsigned*>(&p0);
            w.y = *reinterpret_cast<unsigned*>(&p1);
            ((uint2*)g_xh)[(size_t)node * 32 + lane] = w;
        }
    }
}

// ---------------------------------------------------------------------------
// K2: single-pass decoupled-lookback scan of deg_in -> g_off, plus norms.
__global__ void __launch_bounds__(SCAN_T)
scan_norm_kernel() {
    __shared__ int sm[SCAN_T];
    __shared__ int s_prefix;
    const int b = blockIdx.x;
    const int tid = threadIdx.x;
    const int i = b * SCAN_T + tid;

    int v = (i < N_NODES) ? DEG_IN[i] : 0;
    if (i < N_NODES) {
        g_norm_out[i] = rsqrtf(fmaxf((float)DEG_OUT[i], 1.0f));
        g_norm_in[i]  = rsqrtf(fmaxf((float)v, 1.0f));
    }
    sm[tid] = v;
    __syncthreads();
    for (int ofs = 1; ofs < SCAN_T; ofs <<= 1) {
        int t = (tid >= ofs) ? sm[tid - ofs] : 0;
        __syncthreads();
        sm[tid] += t;
        __syncthreads();
    }

    if (tid == 0) {
        int total = sm[SCAN_T - 1];
        g_scan_agg[b] = total;
        __threadfence();
        atomicExch(&SFLAG[b], 1);

        int p = 0;
        for (int j = b - 1; j >= 0; --j) {
            int f;
            do { f = atomicAdd(&SFLAG[j], 0); } while (f == 0);
            __threadfence();
            if (f == 2) { p += g_scan_pref[j]; break; }
            p += g_scan_agg[j];
        }
        g_scan_pref[b] = p + total;
        __threadfence();
        atomicExch(&SFLAG[b], 2);
        s_prefix = p;
    }
    __syncthreads();

    if (i < N_NODES) g_off[i + 1] = sm[tid] + s_prefix;
    if (i == 0) g_off[0] = 0;
}

// ---------------------------------------------------------------------------
// K3: fused — CSR fill + W1^T fp16 + Wcomb^T fp16 + bcomb
#define FILL_B  ((N_EDGES + 255) / 256)        // 6250
#define W1T_B   ((HDIM * HDIM) / 256)          // 64
#define WC_B    (HDIM + 1)                     // 129
#define K3_GRID (FILL_B + W1T_B + WC_B)

__global__ void __launch_bounds__(256)
fill_prep_kernel(const int* __restrict__ src, const int* __restrict__ dst,
                 const float* __restrict__ W1,
                 const float* __restrict__ W2, const float* __restrict__ Wfc,
                 const float* __restrict__ b2, const float* __restrict__ bfc) {
    const int bid = blockIdx.x;
    const int tid = threadIdx.x;

    if (bid < FILL_B) {
        int e = bid * 256 + tid;
        if (e < N_EDGES) {
            int d = dst[e];
            int pos = g_off[d] + atomicAdd(&CURSOR[d], 1);
            g_csr_src[pos] = src[e];
        }
    } else if (bid < FILL_B + W1T_B) {
        int idx = (bid - FILL_B) * 256 + tid;            // over 16384 elems
        int k = idx >> 7;
        int n = idx & 127;
        g_w1ht[n * HDIM + k] = __float2half_rn(W1[k * HDIM + n]);
    } else {
        int j = bid - FILL_B - W1T_B;                    // 0..128; j<128: row j of W2
        __shared__ float row[HDIM];
        const float* srcrow = (j < HDIM) ? (W2 + j * HDIM) : b2;
        if (tid < HDIM) row[tid] = srcrow[tid];
        __syncthreads();
        if (tid < CDIM) {
            float acc = (j < HDIM) ? 0.f : bfc[tid];
#pragma unroll 8
            for (int k = 0; k < HDIM; k++)
                acc = fmaf(row[k], Wfc[k * CDIM + tid], acc);
            if (j < HDIM) g_wcombh[tid * HDIM + j] = __float2half_rn(acc);
            else          g_bcomb[tid] = acc;
        }
    }
}

// ---------------------------------------------------------------------------
// fp16-row accumulate helpers
__device__ __forceinline__ void acc_half_row(const uint2* __restrict__ base,
                                             int s, int lane, float4& acc) {
    uint2 r = __ldg(base + (size_t)s * 32 + lane);
    __half2 h0 = *reinterpret_cast<__half2*>(&r.x);
    __half2 h1 = *reinterpret_cast<__half2*>(&r.y);
    float2 f0 = __half22float2(h0);
    float2 f1 = __half22float2(h1);
    acc.x += f0.x; acc.y += f0.y; acc.z += f1.x; acc.w += f1.y;
}

__device__ __forceinline__ void acc_half_row_scaled(const uint2* __restrict__ base,
                                                    int s, float sc, int lane, float4& acc) {
    uint2 r = __ldg(base + (size_t)s * 32 + lane);
    __half2 h0 = *reinterpret_cast<__half2*>(&r.x);
    __half2 h1 = *reinterpret_cast<__half2*>(&r.y);
    float2 f0 = __half22float2(h0);
    float2 f1 = __half22float2(h1);
    acc.x = fmaf(f0.x, sc, acc.x); acc.y = fmaf(f0.y, sc, acc.y);
    acc.z = fmaf(f1.x, sc, acc.z); acc.w = fmaf(f1.y, sc, acc.w);
}

__device__ __forceinline__ void store_half4(__half* dst, size_t node, int lane,
                                            const float4& acc, float scale) {
    __half2 p0 = __floats2half2_rn(acc.x * scale, acc.y * scale);
    __half2 p1 = __floats2half2_rn(acc.z * scale, acc.w * scale);
    uint2 w;
    w.x = *reinterpret_cast<unsigned*>(&p0);
    w.y = *reinterpret_cast<unsigned*>(&p1);
    ((uint2*)dst)[node * 32 + lane] = w;
}

// ---------------------------------------------------------------------------
// K4 (PROFILED): gather1 (warp per node, high occupancy):
//   a1h[n,:] = fp16( norm_in[n] * sum_{s in N_in(n)} xh[s,:] * norm_out[s] )
__global__ void __launch_bounds__(256)
gather1_kernel() {
    int t    = blockIdx.x * blockDim.x + threadIdx.x;
    int node = t >> 5;
    int lane = t & 31;
    if (node >= N_NODES) return;

    int beg = g_off[node];
    int end = g_off[node + 1];
    const uint2* xin = (const uint2*)g_xh;

    float4 acc = make_float4(0.f, 0.f, 0.f, 0.f);
    int j = beg;
    for (; j + 4 <= end; j += 4) {
        int s0 = g_csr_src[j + 0];
        int s1 = g_csr_src[j + 1];
        int s2 = g_csr_src[j + 2];
        int s3 = g_csr_src[j + 3];
        acc_half_row_scaled(xin, s0, g_norm_out[s0], lane, acc);
        acc_half_row_scaled(xin, s1, g_norm_out[s1], lane, acc);
        acc_half_row_scaled(xin, s2, g_norm_out[s2], lane, acc);
        acc_half_row_scaled(xin, s3, g_norm_out[s3], lane, acc);
    }
    for (; j < end; j++) {
        int s = g_csr_src[j];
        acc_half_row_scaled(xin, s, g_norm_out[s], lane, acc);
    }

    store_half4(g_a1h, (size_t)node, lane, acc, g_norm_in[node]);
}

// ---------------------------------------------------------------------------
// K5: HMMA GEMM: h1h[n,:] = fp16( relu(a1h[n,:] @ W1 + b1) * norm_out[n] )
#define GEMM_SMEM (2 * HDIM * APAD * (int)sizeof(__half))   // 69632 B

__global__ void __launch_bounds__(256)
gemm_hmma_kernel(const float* __restrict__ bias) {
    extern __shared__ __half smem[];
    __half* As = smem;                    // [128][APAD]
    __half* Ws = smem + HDIM * APAD;      // [128][APAD]  (W1^T: [n][k])
    __shared__ float bs[HDIM];

    const int tid = threadIdx.x;
    const int block_row = blockIdx.x * 128;

    if (tid < HDIM) bs[tid] = bias[tid];

#pragma unroll
    for (int t = 0; t < 8; t++) {
        int idx = tid + t * 256;
        int r   = idx >> 4;
        int c8  = (idx & 15) << 3;
        int n   = block_row + r;
        uint4 v = make_uint4(0u, 0u, 0u, 0u);
        if (n < N_NODES) v = *(const uint4*)(g_a1h + (size_t)n * HDIM + c8);
        *(uint4*)(As + r * APAD + c8) = v;
        *(uint4*)(Ws + r * APAD + c8) = *(const uint4*)(g_w1ht + r * HDIM + c8);
    }
    __syncthreads();

    const int warp  = tid >> 5;
    const int lane  = tid & 31;
    const int warpM = warp & 3;
    const int warpN = warp >> 2;
    const int lr    = lane >> 2;
    const int lc    = (lane & 3) << 1;

    float acc[2][8][4];
#pragma unroll
    for (int m = 0; m < 2; m++)
#pragma unroll
        for (int n = 0; n < 8; n++)
#pragma unroll
            for (int q = 0; q < 4; q++) acc[m][n][q] = 0.f;

#pragma unroll
    for (int k16 = 0; k16 < 8; k16++) {
        const int kb = k16 * 16 + lc;
        unsigned a[2][4];
#pragma unroll
        for (int m = 0; m < 2; m++) {
            const __half* ap = As + (warpM * 32 + m * 16 + lr) * APAD;
            a[m][0] = *(const unsigned*)(ap + kb);
            a[m][1] = *(const unsigned*)(ap + 8 * APAD + kb);
            a[m][2] = *(const unsigned*)(ap + kb + 8);
            a[m][3] = *(const unsigned*)(ap + 8 * APAD + kb + 8);
        }
#pragma unroll
        for (int n = 0; n < 8; n++) {
            const __half* bp = Ws + (warpN * 64 + n * 8 + lr) * APAD + kb;
            unsigned b0 = *(const unsigned*)(bp);
            unsigned b1 = *(const unsigned*)(bp + 8);
#pragma unroll
            for (int m = 0; m < 2; m++) {
                asm volatile(
                    "mma.sync.aligned.m16n8k16.row.col.f32.f16.f16.f32 "
                    "{%0,%1,%2,%3}, {%4,%5,%6,%7}, {%8,%9}, {%0,%1,%2,%3};"
                    : "+f"(acc[m][n][0]), "+f"(acc[m][n][1]),
                      "+f"(acc[m][n][2]), "+f"(acc[m][n][3])
                    : "r"(a[m][0]), "r"(a[m][1]), "r"(a[m][2]), "r"(a[m][3]),
                      "r"(b0), "r"(b1));
            }
        }
    }

#pragma unroll
    for (int m = 0; m < 2; m++) {
        int r0 = block_row + warpM * 32 + m * 16 + lr;
        int r1 = r0 + 8;
        float no0 = (r0 < N_NODES) ? g_norm_out[r0] : 0.f;
        float no1 = (r1 < N_NODES) ? g_norm_out[r1] : 0.f;
#pragma unroll
        for (int n = 0; n < 8; n++) {
            int col = warpN * 64 + n * 8 + lc;
            float bb0 = bs[col], bb1 = bs[col + 1];
            if (r0 < N_NODES) {
                __half2 h = __floats2half2_rn(fmaxf(acc[m][n][0] + bb0, 0.f) * no0,
                                              fmaxf(acc[m][n][1] + bb1, 0.f) * no0);
                *(__half2*)(g_h1h + (size_t)r0 * HDIM + col) = h;
            }
            if (r1 < N_NODES) {
                __half2 h = __floats2half2_rn(fmaxf(acc[m][n][2] + bb0, 0.f) * no1,
                                              fmaxf(acc[m][n][3] + bb1, 0.f) * no1);
                *(__half2*)(g_h1h + (size_t)r1 * HDIM + col) = h;
            }
        }
    }
}

// ---------------------------------------------------------------------------
// K6: gather2 (warp per node): a2h[n,:] = fp16( norm_in[n] * sum_{s} h1h[s,:] )
// writes into g_xh (dead after gather1)
__global__ void __launch_bounds__(256)
gather2_kernel() {
    int t    = blockIdx.x * blockDim.x + threadIdx.x;
    int node = t >> 5;
    int lane = t & 31;
    if (node >= N_NODES) return;

    int beg = g_off[node];
    int end = g_off[node + 1];
    const uint2* hin = (const uint2*)g_h1h;

    float4 acc = make_float4(0.f, 0.f, 0.f, 0.f);
    int j = beg;
    for (; j + 8 <= end; j += 8) {
#pragma unroll
        for (int u = 0; u < 8; u++) acc_half_row(hin, g_csr_src[j + u], lane, acc);
    }
    for (; j < end; j++) acc_half_row(hin, g_csr_src[j], lane, acc);

    store_half4(g_xh, (size_t)node, lane, acc, g_norm_in[node]);
}

// ---------------------------------------------------------------------------
// K7: HMMA FC: out[n, 0:40] = a2h[n,:] @ Wcomb + bcomb  (N=40 = 5 n-frags)
__global__ void __launch_bounds__(256)
fc_hmma_kernel(float* __restrict__ out) {
    __shared__ __half As[HDIM * APAD];    // [128][APAD]  (~34 KB)
    __shared__ __half Wc[CDIM * APAD];    // [40][APAD]   (~10.6 KB)
    __shared__ float bsh[CDIM];

    const int tid  = threadIdx.x;
    const int warp = tid >> 5;
    const int lane = tid & 31;
    const int block_row = blockIdx.x * 128;

    if (tid < CDIM) bsh[tid] = g_bcomb[tid];

    // stage A tile (a2h lives in g_xh) and Wcomb^T
#pragma unroll
    for (int t = 0; t < 8; t++) {
        int idx = tid + t * 256;
        int r   = idx >> 4;
        int c8  = (idx & 15) << 3;
        int n   = block_row + r;
        uint4 v = make_uint4(0u, 0u, 0u, 0u);
        if (n < N_NODES) v = *(const uint4*)(g_xh + (size_t)n * HDIM + c8);
        *(uint4*)(As + r * APAD + c8) = v;
    }
    for (int idx = tid; idx < (CDIM * HDIM) / 8; idx += 256) {
        int r  = idx >> 4;
        int c8 = (idx & 15) << 3;
        *(uint4*)(Wc + r * APAD + c8) = ((const uint4*)g_wcombh)[idx];
    }
    __syncthreads();

    const int lr = lane >> 2;
    const int lc = (lane & 3) << 1;

    float acc[5][4];
#pragma unroll
    for (int n = 0; n < 5; n++)
#pragma unroll
        for (int q = 0; q < 4; q++) acc[n][q] = 0.f;

#pragma unroll
    for (int k16 = 0; k16 < 8; k16++) {
        const int kb = k16 * 16 + lc;
        const __half* ap = As + (warp * 16 + lr) * APAD;
        unsigned a0 = *(const unsigned*)(ap + kb);
        unsigned a1 = *(const unsigned*)(ap + 8 * APAD + kb);
        unsigned a2 = *(const unsigned*)(ap + kb + 8);
        unsigned a3 = *(const unsigned*)(ap + 8 * APAD + kb + 8);
#pragma unroll
        for (int n = 0; n < 5; n++) {
            const __half* bp = Wc + (n * 8 + lr) * APAD + kb;
            unsigned b0 = *(const unsigned*)(bp);
            unsigned b1 = *(const unsigned*)(bp + 8);
            asm volatile(
                "mma.sync.aligned.m16n8k16.row.col.f32.f16.f16.f32 "
                "{%0,%1,%2,%3}, {%4,%5,%6,%7}, {%8,%9}, {%0,%1,%2,%3};"
                : "+f"(acc[n][0]), "+f"(acc[n][1]), "+f"(acc[n][2]), "+f"(acc[n][3])
                : "r"(a0), "r"(a1), "r"(a2), "r"(a3), "r"(b0), "r"(b1));
        }
    }

    int r0 = block_row + warp * 16 + lr;
    int r1 = r0 + 8;
#pragma unroll
    for (int n = 0; n < 5; n++) {
        int col = n * 8 + lc;
        float b0 = bsh[col], b1 = bsh[col + 1];
        if (r0 < N_NODES) {
            float2 v = make_float2(acc[n][0] + b0, acc[n][1] + b1);
            *(float2*)(out + (size_t)r0 * CDIM + col) = v;
        }
        if (r1 < N_NODES) {
            float2 v = make_float2(acc[n][2] + b0, acc[n][3] + b1);
            *(float2*)(out + (size_t)r1 * CDIM + col) = v;
        }
    }
}

// ---------------------------------------------------------------------------
extern "C" void kernel_launch(void* const* d_in, const int* in_sizes, int n_in,
                              void* d_out, int out_size) {
    const float* x   = (const float*)d_in[0];
    const int*   ei  = (const int*)  d_in[1];
    const float* W1  = (const float*)d_in[2];
    const float* b1  = (const float*)d_in[3];
    const float* W2  = (const float*)d_in[4];
    const float* b2  = (const float*)d_in[5];
    const float* Wfc = (const float*)d_in[6];
    const float* bfc = (const float*)d_in[7];
    float* out = (float*)d_out;

    const int* src = ei;            // edge_index row 0
    const int* dst = ei + N_EDGES;  // edge_index row 1

    int* p_ints;
    cudaGetSymbolAddress((void**)&p_ints, g_ints);

    static bool attr_set = false;
    if (!attr_set) {
        cudaFuncSetAttribute(gemm_hmma_kernel,
                             cudaFuncAttributeMaxDynamicSharedMemorySize, GEMM_SMEM);
        attr_set = true;
    }

    const int agg_blocks  = (N_NODES * 32 + 255) / 256;   // 12500
    const int node_blocks = (N_NODES + 127) / 128;        // 782

    // zero [deg_out | deg_in | cursor | scan flags]
    cudaMemsetAsync(p_ints, 0, (3 * N_NODES + 128) * sizeof(int));
    // K1: degrees + x->fp16 cast
    deg_conv_kernel<<<K1_GRID, 256>>>(src, dst, x);
    // K2: lookback scan + norms
    scan_norm_kernel<<<SCAN_BLOCKS, SCAN_T>>>();
    // K3: CSR fill + W1^T fp16 + Wcomb^T fp16 + bcomb
    fill_prep_kernel<<<K3_GRID, 256>>>(src, dst, W1, W2, Wfc, b2, bfc);
    // K4 (profiled): gather1 -> a1h fp16 (high occupancy)
    gather1_kernel<<<agg_blocks, 256>>>();
    // K5: HMMA GEMM -> h1h fp16
    gemm_hmma_kernel<<<node_blocks, 256, GEMM_SMEM>>>(b1);
    // K6: gather2 -> a2h fp16 (reuses g_xh)
    gather2_kernel<<<agg_blocks, 256>>>();
    // K7: HMMA FC -> out
    fc_hmma_kernel<<<node_blocks, 256>>>(out);
}